// round 5
// baseline (speedup 1.0000x reference)
#include <cuda_runtime.h>

// Problem constants
#define DD 300
#define LL 128
#define BC 2048                    // B*C = 32*64
#define NROWS (BC * LL)            // 262144 output rows
#define THREADS 64
#define NTHREADS_TOTAL (NROWS / 4) // one thread per 4 rows => 65536 threads
#define UB 4                       // d-batch: 300 = 4 * 75

__global__ void __launch_bounds__(THREADS, 12)
hcmp_kernel(const float* __restrict__ x,
            const float* __restrict__ y,
            float* __restrict__ out)
{
    const int t = blockIdx.x * THREADS + threadIdx.x;
    const int row0 = t * 4;                       // rows row0..row0+3
    const int slab = row0 >> 7;                   // (b*C + c)
    const int l0 = row0 & (LL - 1);               // multiple of 4

    // float4 view: element (slab, d, l0..l0+3) at x + slab*D*L + d*L + l0
    const float4* __restrict__ xp =
        reinterpret_cast<const float4*>(x + (size_t)slab * (DD * LL) + l0);
    const float4* __restrict__ yp =
        reinterpret_cast<const float4*>(y + (size_t)slab * (DD * LL) + l0);
    // stride per d in float4 units = L/4 = 32

    float sxx[4] = {0.f,0.f,0.f,0.f};
    float syy[4] = {0.f,0.f,0.f,0.f};
    float sxy[4] = {0.f,0.f,0.f,0.f};
    float sl1[4] = {0.f,0.f,0.f,0.f};
    float sdd[4] = {0.f,0.f,0.f,0.f};

    for (int d = 0; d < DD; d += UB) {
        float4 xa[UB], ya[UB];
        #pragma unroll
        for (int u = 0; u < UB; u++)
            xa[u] = __ldcs(xp + (d + u) * (LL / 4));
        #pragma unroll
        for (int u = 0; u < UB; u++)
            ya[u] = __ldcs(yp + (d + u) * (LL / 4));

        #pragma unroll
        for (int u = 0; u < UB; u++) {
            float xv[4] = {xa[u].x, xa[u].y, xa[u].z, xa[u].w};
            float yv[4] = {ya[u].x, ya[u].y, ya[u].z, ya[u].w};
            #pragma unroll
            for (int j = 0; j < 4; j++) {
                float df = xv[j] - yv[j];
                sxx[j] = fmaf(xv[j], xv[j], sxx[j]);
                syy[j] = fmaf(yv[j], yv[j], syy[j]);
                sxy[j] = fmaf(xv[j], yv[j], sxy[j]);
                sdd[j] = fmaf(df, df, sdd[j]);
                sl1[j] += fabsf(df);
            }
        }
    }

    // Epilogue: 4 rows => 12 contiguous floats at row0*3 (16B-aligned: 48t bytes).
    float res[12];
    #pragma unroll
    for (int j = 0; j < 4; j++) {
        float nx = fmaxf(sqrtf(sxx[j]), 1e-12f);
        float ny = fmaxf(sqrtf(syy[j]), 1e-12f);
        float cosv = sxy[j] / (nx * ny);
        float sq = sdd[j];
        if (sq < 1e-8f) sq += 1e-8f;   // revise_zero_data
        res[j * 3 + 0] = cosv;
        res[j * 3 + 1] = sqrtf(sq);
        res[j * 3 + 2] = sl1[j];
    }

    float4* o4 = reinterpret_cast<float4*>(out + (size_t)row0 * 3);
    o4[0] = make_float4(res[0], res[1], res[2],  res[3]);
    o4[1] = make_float4(res[4], res[5], res[6],  res[7]);
    o4[2] = make_float4(res[8], res[9], res[10], res[11]);
}

extern "C" void kernel_launch(void* const* d_in, const int* in_sizes, int n_in,
                              void* d_out, int out_size)
{
    const float* x = (const float*)d_in[0];
    const float* y = (const float*)d_in[1];
    float* out = (float*)d_out;

    dim3 grid(NTHREADS_TOTAL / THREADS);   // 1024 blocks
    dim3 block(THREADS);                   // 64 threads
    hcmp_kernel<<<grid, block>>>(x, y, out);
}

// round 6
// speedup vs baseline: 1.0357x; 1.0357x over previous
#include <cuda_runtime.h>

// Problem constants
#define DD 300
#define LL 128
#define BC 2048                   // B*C = 32*64
#define NROWS (BC * LL)           // 262144 output rows
#define THREADS 64                // small blocks => fine-grain scheduling
#define NTHREADS_TOTAL (NROWS / 2)   // one thread per 2 rows => 131072 threads
#define UB 10                     // d-batch: 300 = 10 * 30

__global__ void __launch_bounds__(THREADS, 12)
hcmp_kernel(const float* __restrict__ x,
            const float* __restrict__ y,
            float* __restrict__ out)
{
    const int t = blockIdx.x * THREADS + threadIdx.x;
    const int row0 = t * 2;                       // rows row0, row0+1
    const int slab = row0 >> 7;                   // (b*C + c)
    const int l0 = row0 & (LL - 1);               // even l

    // float2 view: element (slab, d, l0..l0+1) at x + slab*D*L + d*L + l0
    const float2* __restrict__ xp =
        reinterpret_cast<const float2*>(x + (size_t)slab * (DD * LL) + l0);
    const float2* __restrict__ yp =
        reinterpret_cast<const float2*>(y + (size_t)slab * (DD * LL) + l0);
    // stride per d in float2 units = L/2 = 64

    float sxx0 = 0.f, syy0 = 0.f, sxy0 = 0.f, sl10 = 0.f, sdd0 = 0.f;
    float sxx1 = 0.f, syy1 = 0.f, sxy1 = 0.f, sl11 = 0.f, sdd1 = 0.f;

    for (int d = 0; d < DD; d += UB) {
        float2 xa[UB], ya[UB];
        #pragma unroll
        for (int u = 0; u < UB; u++)
            xa[u] = __ldcs(xp + (d + u) * (LL / 2));
        #pragma unroll
        for (int u = 0; u < UB; u++)
            ya[u] = __ldcs(yp + (d + u) * (LL / 2));

        #pragma unroll
        for (int u = 0; u < UB; u++) {
            float xv0 = xa[u].x, yv0 = ya[u].x;
            float df0 = xv0 - yv0;
            sxx0 = fmaf(xv0, xv0, sxx0);
            syy0 = fmaf(yv0, yv0, syy0);
            sxy0 = fmaf(xv0, yv0, sxy0);
            sdd0 = fmaf(df0, df0, sdd0);
            sl10 += fabsf(df0);

            float xv1 = xa[u].y, yv1 = ya[u].y;
            float df1 = xv1 - yv1;
            sxx1 = fmaf(xv1, xv1, sxx1);
            syy1 = fmaf(yv1, yv1, syy1);
            sxy1 = fmaf(xv1, yv1, sxy1);
            sdd1 = fmaf(df1, df1, sdd1);
            sl11 += fabsf(df1);
        }
    }

    // Epilogue for both rows; outputs are 6 contiguous floats at row0*3.
    float nx0 = fmaxf(sqrtf(sxx0), 1e-12f);
    float ny0 = fmaxf(sqrtf(syy0), 1e-12f);
    float cos0 = sxy0 / (nx0 * ny0);
    float sq0 = sdd0;
    if (sq0 < 1e-8f) sq0 += 1e-8f;
    float l20 = sqrtf(sq0);

    float nx1 = fmaxf(sqrtf(sxx1), 1e-12f);
    float ny1 = fmaxf(sqrtf(syy1), 1e-12f);
    float cos1 = sxy1 / (nx1 * ny1);
    float sq1 = sdd1;
    if (sq1 < 1e-8f) sq1 += 1e-8f;
    float l21 = sqrtf(sq1);

    float* o = out + (size_t)row0 * 3;
    o[0] = cos0;
    o[1] = l20;
    o[2] = sl10;
    o[3] = cos1;
    o[4] = l21;
    o[5] = sl11;
}

extern "C" void kernel_launch(void* const* d_in, const int* in_sizes, int n_in,
                              void* d_out, int out_size)
{
    const float* x = (const float*)d_in[0];
    const float* y = (const float*)d_in[1];
    float* out = (float*)d_out;

    dim3 grid(NTHREADS_TOTAL / THREADS);   // 2048 blocks
    dim3 block(THREADS);                   // 64 threads = 2 warps
    hcmp_kernel<<<grid, block>>>(x, y, out);
}